// round 1
// baseline (speedup 1.0000x reference)
#include <cuda_runtime.h>
#include <cstdint>

// Problem constants
#define BB 32
#define SS 2048
#define DD 512
#define UU 512
#define ROWS (BB*SS)          // 65536
#define NTILES 4              // U / 128
#define MTILES 512            // ROWS / 128

// -------- scratch (no allocation allowed) --------
__device__ float g_hp[BB*UU];                 // h_proj  [32][512]
__device__ float g_partial[NTILES][ROWS];     // per-n-tile partial scores
__device__ float g_ctxpart[BB*16*DD];         // per-s-chunk context partials

// -------- packed f32x2 helpers --------
__device__ __forceinline__ unsigned long long splat2(float x) {
    unsigned long long r;
    asm("mov.b64 %0, {%1, %1};" : "=l"(r) : "f"(x));
    return r;
}
__device__ __forceinline__ void fma2(unsigned long long &d, unsigned long long a, unsigned long long b) {
    asm("fma.rn.f32x2 %0, %1, %2, %0;" : "+l"(d) : "l"(a), "l"(b));
}
__device__ __forceinline__ float2 unpack2(unsigned long long v) {
    float2 r;
    asm("mov.b64 {%0, %1}, %2;" : "=f"(r.x), "=f"(r.y) : "l"(v));
    return r;
}

// =====================================================================
// Phase A: h_proj[b][u] = sum_d hidden[b][d] * W2[d][u]
// =====================================================================
__global__ void hproj_kernel(const float* __restrict__ hidden,
                             const float* __restrict__ W2) {
    __shared__ float h_s[DD];
    const int b = blockIdx.x;
    for (int d = threadIdx.x; d < DD; d += blockDim.x)
        h_s[d] = hidden[b*DD + d];
    __syncthreads();
    const int u = threadIdx.x;   // blockDim = 512
    float acc = 0.f;
#pragma unroll 8
    for (int d = 0; d < DD; d++)
        acc = fmaf(h_s[d], W2[d*UU + u], acc);
    g_hp[b*UU + u] = acc;
}

// =====================================================================
// Phase B: fused GEMM + tanh + Vw-reduce.
// Block tile 128(M rows) x 128(N=u), K=512 in slabs of 8.
// 256 threads, 8x8 micro-tile per thread, f32x2 packed FMAs.
// Epilogue: partial_score[row] += sum_u tanh(pp + hp[u]) * Vw[u]
// written per n-tile (deterministic, no atomics).
// =====================================================================
__global__ __launch_bounds__(256)
void score_gemm(const float* __restrict__ passage,
                const float* __restrict__ W1,
                const float* __restrict__ Vw) {
    const int nt  = blockIdx.x;          // 0..3
    const int mt  = blockIdx.y;          // 0..511
    const int n0  = nt * 128;
    const int m0  = mt * 128;
    const int b   = m0 >> 11;            // all 128 rows share one batch (2048/128=16)
    const int tid = threadIdx.x;
    const int tx  = tid & 15;            // n direction (16)
    const int ty  = tid >> 4;            // m direction (16)

    __shared__ float As[8][128];         // [k][m]
    __shared__ float Bs[8][128];         // [k][n]
    __shared__ float hp_s[128];
    __shared__ float vw_s[128];
    __shared__ float red[128][17];       // padded reduction buffer

    if (tid < 128) {
        hp_s[tid] = g_hp[b*UU + n0 + tid];
        vw_s[tid] = Vw[n0 + tid];
    }

    unsigned long long acc[8][4];
#pragma unroll
    for (int i = 0; i < 8; i++)
#pragma unroll
        for (int j = 0; j < 4; j++) acc[i][j] = 0ull;

    // A (passage) load mapping: 128 rows x 8 k per slab, float4 per thread
    const int arow = tid >> 1;
    const int akq  = (tid & 1) * 4;
    const float* aptr = passage + (size_t)(m0 + arow) * DD + akq;
    // B (W1) load mapping: 8 k x 128 n per slab, float4 per thread
    const int bkk = tid >> 5;
    const int buq = (tid & 31) * 4;
    const float* bptr = W1 + (size_t)bkk * UU + n0 + buq;

    float4 av = *(const float4*)(aptr);
    float4 bv = *(const float4*)(bptr);

    for (int k0 = 0; k0 < DD; k0 += 8) {
        As[akq + 0][arow] = av.x;
        As[akq + 1][arow] = av.y;
        As[akq + 2][arow] = av.z;
        As[akq + 3][arow] = av.w;
        *(float4*)&Bs[bkk][buq] = bv;
        __syncthreads();

        if (k0 + 8 < DD) {   // prefetch next slab while computing
            av = *(const float4*)(aptr + k0 + 8);
            bv = *(const float4*)(bptr + (size_t)(k0 + 8) * UU);
        }

#pragma unroll
        for (int k = 0; k < 8; k++) {
            float4 a0 = *(const float4*)&As[k][ty*8];
            float4 a1 = *(const float4*)&As[k][ty*8 + 4];
            // Bs pairs reinterpreted directly as packed f32x2 operands
            ulonglong2 bq0 = *(const ulonglong2*)&Bs[k][tx*8];
            ulonglong2 bq1 = *(const ulonglong2*)&Bs[k][tx*8 + 4];
            unsigned long long bp[4] = { bq0.x, bq0.y, bq1.x, bq1.y };

            unsigned long long as_[8];
            as_[0] = splat2(a0.x); as_[1] = splat2(a0.y);
            as_[2] = splat2(a0.z); as_[3] = splat2(a0.w);
            as_[4] = splat2(a1.x); as_[5] = splat2(a1.y);
            as_[6] = splat2(a1.z); as_[7] = splat2(a1.w);

#pragma unroll
            for (int i = 0; i < 8; i++)
#pragma unroll
                for (int j = 0; j < 4; j++)
                    fma2(acc[i][j], as_[i], bp[j]);
        }
        __syncthreads();
    }

    // Epilogue: tanh + Vw partial reduce over this block's 128 u values
#pragma unroll
    for (int i = 0; i < 8; i++) {
        float p = 0.f;
#pragma unroll
        for (int j = 0; j < 4; j++) {
            float2 v = unpack2(acc[i][j]);
            const int n = tx*8 + j*2;
            p = fmaf(tanhf(v.x + hp_s[n]),     vw_s[n],     p);
            p = fmaf(tanhf(v.y + hp_s[n + 1]), vw_s[n + 1], p);
        }
        red[ty*8 + i][tx] = p;
    }
    __syncthreads();

    if (tid < 128) {
        float s = 0.f;
#pragma unroll
        for (int x = 0; x < 16; x++) s += red[tid][x];
        g_partial[nt][m0 + tid] = s;
    }
}

// =====================================================================
// Phase C1: per-batch softmax over S=2048; writes attention weights
// into d_out at offset B*D (context first, weights second).
// =====================================================================
__global__ void softmax_kernel(const float* __restrict__ mask,
                               const float* __restrict__ Vb,
                               float* __restrict__ out) {
    const int b   = blockIdx.x;     // 32
    const int tid = threadIdx.x;    // 256
    __shared__ float sc[SS];
    __shared__ float red[256];

    const float vb = Vb[0];
    float lmax = -1e38f;
#pragma unroll
    for (int i = 0; i < 8; i++) {
        const int s = tid + i*256;
        float v = g_partial[0][b*SS + s] + g_partial[1][b*SS + s]
                + g_partial[2][b*SS + s] + g_partial[3][b*SS + s] + vb;
        v += (1.0f - mask[b*SS + s]) * -1e30f;
        sc[s] = v;
        lmax = fmaxf(lmax, v);
    }
    red[tid] = lmax;
    __syncthreads();
    for (int st = 128; st > 0; st >>= 1) {
        if (tid < st) red[tid] = fmaxf(red[tid], red[tid + st]);
        __syncthreads();
    }
    const float m = red[0];
    __syncthreads();

    float lsum = 0.f;
#pragma unroll
    for (int i = 0; i < 8; i++) {
        const int s = tid + i*256;
        float e = __expf(sc[s] - m) ;
        e = expf(sc[s] - m);   // accurate expf for precision
        sc[s] = e;
        lsum += e;
    }
    red[tid] = lsum;
    __syncthreads();
    for (int st = 128; st > 0; st >>= 1) {
        if (tid < st) red[tid] += red[tid + st];
        __syncthreads();
    }
    const float inv = 1.0f / red[0];
#pragma unroll
    for (int i = 0; i < 8; i++) {
        const int s = tid + i*256;
        out[BB*DD + b*SS + s] = sc[s] * inv;
    }
}

// =====================================================================
// Phase C2: partial context over s-chunks of 128 (deterministic)
// =====================================================================
__global__ void ctx_part_kernel(const float* __restrict__ passage,
                                const float* __restrict__ out_r) {
    const int c = blockIdx.x;   // 16 s-chunks
    const int b = blockIdx.y;   // 32
    const int d = threadIdx.x;  // 512
    __shared__ float w_s[128];
    if (d < 128) w_s[d] = out_r[BB*DD + b*SS + c*128 + d];
    __syncthreads();
    float acc = 0.f;
    const float* p = passage + ((size_t)b*SS + c*128) * DD + d;
#pragma unroll 4
    for (int s = 0; s < 128; s++)
        acc = fmaf(w_s[s], p[(size_t)s * DD], acc);
    g_ctxpart[(b*16 + c)*DD + d] = acc;
}

// =====================================================================
// Phase C3: reduce 16 chunk-partials -> context output
// =====================================================================
__global__ void ctx_reduce(float* __restrict__ out) {
    const int b = blockIdx.x;   // 32
    const int d = threadIdx.x;  // 512
    float s = 0.f;
#pragma unroll
    for (int c = 0; c < 16; c++) s += g_ctxpart[(b*16 + c)*DD + d];
    out[b*DD + d] = s;
}

// =====================================================================
extern "C" void kernel_launch(void* const* d_in, const int* in_sizes, int n_in,
                              void* d_out, int out_size) {
    const float* passage = (const float*)d_in[0];  // [32,2048,512]
    const float* hidden  = (const float*)d_in[1];  // [32,512]
    const float* mask    = (const float*)d_in[2];  // [32,2048]
    const float* W1      = (const float*)d_in[3];  // [512,512]
    const float* W2      = (const float*)d_in[4];  // [512,512]
    const float* Vw      = (const float*)d_in[5];  // [512,1]
    const float* Vb      = (const float*)d_in[6];  // [1]
    float* out = (float*)d_out;                    // [32*512 ctx | 32*2048 attn]

    hproj_kernel<<<BB, DD>>>(hidden, W2);
    score_gemm<<<dim3(NTILES, MTILES), 256>>>(passage, W1, Vw);
    softmax_kernel<<<BB, 256>>>(mask, Vb, out);
    ctx_part_kernel<<<dim3(16, BB), DD>>>(passage, out);
    ctx_reduce<<<BB, DD>>>(out);
}

// round 3
// speedup vs baseline: 1.8597x; 1.8597x over previous
#include <cuda_runtime.h>
#include <cuda_bf16.h>
#include <cstdint>

#define BB 32
#define SS 2048
#define DD 512
#define UU 512
#define ROWS (BB*SS)          // 65536
#define NTILES 4
#define PITCH 80              // smem row pitch in bytes (conflict-free for ldmatrix)

// ---------------- scratch (no allocation allowed) ----------------
__device__ float g_hp[BB*UU];                  // h_proj
__device__ float g_partial[NTILES][ROWS];      // per-n-tile partial scores
__device__ float g_ctxpart[BB*16*DD];          // context partials
__device__ __nv_bfloat16 g_Bhi[UU*DD];         // W1^T hi  [u][k]
__device__ __nv_bfloat16 g_Blo[UU*DD];         // W1^T lo  [u][k]

// ---------------- helpers ----------------
__device__ __forceinline__ uint32_t smem_u32(const void* p) {
    uint32_t a;
    asm("{ .reg .u64 t; cvta.to.shared.u64 t, %1; cvt.u32.u64 %0, t; }" : "=r"(a) : "l"(p));
    return a;
}
__device__ __forceinline__ void ldsm_x4(uint32_t addr, uint32_t &r0, uint32_t &r1,
                                        uint32_t &r2, uint32_t &r3) {
    asm volatile("ldmatrix.sync.aligned.m8n8.x4.shared.b16 {%0,%1,%2,%3}, [%4];"
        : "=r"(r0), "=r"(r1), "=r"(r2), "=r"(r3) : "r"(addr));
}
__device__ __forceinline__ void mma_bf16(float* d, const uint32_t* a,
                                         uint32_t b0, uint32_t b1) {
    asm volatile("mma.sync.aligned.m16n8k16.row.col.f32.bf16.bf16.f32 "
        "{%0,%1,%2,%3}, {%4,%5,%6,%7}, {%8,%9}, {%0,%1,%2,%3};"
        : "+f"(d[0]), "+f"(d[1]), "+f"(d[2]), "+f"(d[3])
        : "r"(a[0]), "r"(a[1]), "r"(a[2]), "r"(a[3]), "r"(b0), "r"(b1));
}

// =====================================================================
// h_proj: [B,U] = hidden @ W2   (exact fp32)
// =====================================================================
__global__ void hproj_kernel(const float* __restrict__ hidden,
                             const float* __restrict__ W2) {
    __shared__ float h_s[DD];
    const int b = blockIdx.x;
    h_s[threadIdx.x] = hidden[b*DD + threadIdx.x];
    __syncthreads();
    const int u = threadIdx.x;
    float acc = 0.f;
#pragma unroll 8
    for (int d = 0; d < DD; d++)
        acc = fmaf(h_s[d], W2[d*UU + u], acc);
    g_hp[b*UU + u] = acc;
}

// =====================================================================
// W1 split/transpose:  g_Bhi/g_Blo[u][k] = bf16-split(W1[k][u])
// =====================================================================
__global__ void w1split(const float* __restrict__ W1) {
    const int n = blockIdx.x;
    const int k = threadIdx.x;
    float v = W1[k*UU + n];
    __nv_bfloat16 hi = __float2bfloat16(v);
    float r = v - __bfloat162float(hi);
    g_Bhi[n*DD + k] = hi;
    g_Blo[n*DD + k] = __float2bfloat16(r);
}

// =====================================================================
// Fused mma.sync score GEMM: CTA tile 128Mx128N, K=512 in 16 chunks of 32.
// 512 threads = 16 warps (4M x 4N), warp tile 32x32.
// 3-product bf16 split. Epilogue: tanh + Vw partial reduce.
// =====================================================================
__global__ __launch_bounds__(512, 1)
void score_gemm_tc(const float* __restrict__ passage, const float* __restrict__ Vw) {
    __shared__ __align__(16) char sAh[128*PITCH];
    __shared__ __align__(16) char sAl[128*PITCH];
    __shared__ __align__(16) char sBh[128*PITCH];
    __shared__ __align__(16) char sBl[128*PITCH];
    __shared__ float hp_s[128];
    __shared__ float vw_s[128];
    __shared__ float red[128][4];

    const int nt = blockIdx.x;       // 0..3
    const int mt = blockIdx.y;       // 0..511
    const int n0 = nt * 128;
    const int m0 = mt * 128;
    const int b  = mt >> 4;
    const int tid = threadIdx.x;
    const int wid = tid >> 5;
    const int lid = tid & 31;
    const int warp_m = wid >> 2;     // 0..3
    const int warp_n = wid & 3;      // 0..3

    if (tid < 128) {
        hp_s[tid] = g_hp[b*UU + n0 + tid];
        vw_s[tid] = Vw[n0 + tid];
    }

    const uint32_t uAh = smem_u32(sAh), uAl = smem_u32(sAl);
    const uint32_t uBh = smem_u32(sBh), uBl = smem_u32(sBl);

    // --- global load mappings ---
    // A: each thread loads 8 floats: row = tid>>2, kq = (tid&3)*8
    const int arow = tid >> 2;
    const int akq  = (tid & 3) * 8;
    const float* aptr = passage + (size_t)(m0 + arow) * DD + akq;
    const uint32_t a_sts = (uint32_t)(arow * PITCH + akq * 2);

    // B: idx = tid&255 over one plane: row = idx>>1, koff = (idx&1)*16 halfs (32B)
    const int bplane = tid >> 8;                 // 0 = hi, 1 = lo
    const int bidx   = tid & 255;
    const int brow   = bidx >> 1;
    const int bkoff  = (bidx & 1) * 16;
    const __nv_bfloat16* bsrc = (bplane ? g_Blo : g_Bhi) + (size_t)(n0 + brow) * DD + bkoff;
    const uint32_t b_sts = (bplane ? uBl : uBh) + (uint32_t)(brow * PITCH + bkoff * 2);

    // ldmatrix per-thread source addresses (fixed row part)
    // tile row within 16: (lid&7) + ((lid>>3)&1)*8 ; k half-tile: (lid>>4)*8
    const int lm_row = (lid & 7) + ((lid >> 3) & 1) * 8;
    const int lm_kof = (lid >> 4) * 8;
    const uint32_t a_lm0 = (uint32_t)((warp_m*32 + lm_row) * PITCH + lm_kof * 2);
    const uint32_t a_lm1 = (uint32_t)((warp_m*32 + 16 + lm_row) * PITCH + lm_kof * 2);
    const uint32_t b_lm0 = (uint32_t)((warp_n*32 + lm_row) * PITCH + lm_kof * 2);
    const uint32_t b_lm1 = (uint32_t)((warp_n*32 + 16 + lm_row) * PITCH + lm_kof * 2);

    float acc[2][4][4];
#pragma unroll
    for (int i = 0; i < 2; i++)
#pragma unroll
        for (int j = 0; j < 4; j++)
#pragma unroll
            for (int k = 0; k < 4; k++) acc[i][j][k] = 0.f;

    // prefetch chunk 0
    float4 f0 = *(const float4*)(aptr);
    float4 f1 = *(const float4*)(aptr + 4);
    uint4  u0 = *(const uint4*)(bsrc);
    uint4  u1 = *(const uint4*)(bsrc + 8);

    for (int c = 0; c < 16; c++) {
        // ---- split A to bf16 hi/lo and store smem ----
        {
            float x[8] = {f0.x, f0.y, f0.z, f0.w, f1.x, f1.y, f1.z, f1.w};
            uint32_t hi[4], lo[4];
#pragma unroll
            for (int j = 0; j < 4; j++) {
                __nv_bfloat16 h0 = __float2bfloat16(x[2*j]);
                __nv_bfloat16 h1 = __float2bfloat16(x[2*j+1]);
                float r0 = x[2*j]   - __bfloat162float(h0);
                float r1 = x[2*j+1] - __bfloat162float(h1);
                __nv_bfloat162 hp; hp.x = h0; hp.y = h1;
                __nv_bfloat162 lp; lp.x = __float2bfloat16(r0); lp.y = __float2bfloat16(r1);
                hi[j] = *(uint32_t*)&hp;
                lo[j] = *(uint32_t*)&lp;
            }
            *(uint4*)(sAh + a_sts) = make_uint4(hi[0], hi[1], hi[2], hi[3]);
            *(uint4*)(sAl + a_sts) = make_uint4(lo[0], lo[1], lo[2], lo[3]);
        }
        // ---- store B plane to smem ----
        {
            char* d = (char*)(bplane ? sBl : sBh) + (brow * PITCH + bkoff * 2);
            *(uint4*)(d)      = u0;
            *(uint4*)(d + 16) = u1;
        }
        __syncthreads();

        if (c < 15) {   // prefetch next chunk
            f0 = *(const float4*)(aptr + (c+1)*32);
            f1 = *(const float4*)(aptr + (c+1)*32 + 4);
            u0 = *(const uint4*)(bsrc + (c+1)*32);
            u1 = *(const uint4*)(bsrc + (c+1)*32 + 8);
        }

        // ---- compute: two k16 steps ----
#pragma unroll
        for (int ks = 0; ks < 2; ks++) {
            const uint32_t ko = ks * 32;   // 16 halfs * 2 bytes
            uint32_t ah[2][4], al[2][4];
            ldsm_x4(uAh + a_lm0 + ko, ah[0][0], ah[0][1], ah[0][2], ah[0][3]);
            ldsm_x4(uAh + a_lm1 + ko, ah[1][0], ah[1][1], ah[1][2], ah[1][3]);
            ldsm_x4(uAl + a_lm0 + ko, al[0][0], al[0][1], al[0][2], al[0][3]);
            ldsm_x4(uAl + a_lm1 + ko, al[1][0], al[1][1], al[1][2], al[1][3]);

            uint32_t bh[4][2], bl[4][2];
            {
                uint32_t r0, r1, r2, r3;
                ldsm_x4(uBh + b_lm0 + ko, r0, r1, r2, r3);
                bh[0][0] = r0; bh[0][1] = r2; bh[1][0] = r1; bh[1][1] = r3;
                ldsm_x4(uBh + b_lm1 + ko, r0, r1, r2, r3);
                bh[2][0] = r0; bh[2][1] = r2; bh[3][0] = r1; bh[3][1] = r3;
                ldsm_x4(uBl + b_lm0 + ko, r0, r1, r2, r3);
                bl[0][0] = r0; bl[0][1] = r2; bl[1][0] = r1; bl[1][1] = r3;
                ldsm_x4(uBl + b_lm1 + ko, r0, r1, r2, r3);
                bl[2][0] = r0; bl[2][1] = r2; bl[3][0] = r1; bl[3][1] = r3;
            }

            // product 1: Ahi * Bhi
#pragma unroll
            for (int mf = 0; mf < 2; mf++)
#pragma unroll
                for (int nf = 0; nf < 4; nf++)
                    mma_bf16(acc[mf][nf], ah[mf], bh[nf][0], bh[nf][1]);
            // product 2: Ahi * Blo
#pragma unroll
            for (int mf = 0; mf < 2; mf++)
#pragma unroll
                for (int nf = 0; nf < 4; nf++)
                    mma_bf16(acc[mf][nf], ah[mf], bl[nf][0], bl[nf][1]);
            // product 3: Alo * Bhi
#pragma unroll
            for (int mf = 0; mf < 2; mf++)
#pragma unroll
                for (int nf = 0; nf < 4; nf++)
                    mma_bf16(acc[mf][nf], al[mf], bh[nf][0], bh[nf][1]);
        }
        __syncthreads();
    }

    // ---- epilogue: tanh + Vw reduce ----
#pragma unroll
    for (int mf = 0; mf < 2; mf++) {
        float plo = 0.f, phi = 0.f;
#pragma unroll
        for (int nf = 0; nf < 4; nf++) {
            const int n = warp_n*32 + nf*8 + (lid & 3)*2;
            const float* cc = acc[mf][nf];
            plo = fmaf(tanhf(cc[0] + hp_s[n]),   vw_s[n],   plo);
            plo = fmaf(tanhf(cc[1] + hp_s[n+1]), vw_s[n+1], plo);
            phi = fmaf(tanhf(cc[2] + hp_s[n]),   vw_s[n],   phi);
            phi = fmaf(tanhf(cc[3] + hp_s[n+1]), vw_s[n+1], phi);
        }
        plo += __shfl_xor_sync(0xffffffff, plo, 1);
        plo += __shfl_xor_sync(0xffffffff, plo, 2);
        phi += __shfl_xor_sync(0xffffffff, phi, 1);
        phi += __shfl_xor_sync(0xffffffff, phi, 2);
        if ((lid & 3) == 0) {
            const int row = warp_m*32 + mf*16 + (lid >> 2);
            red[row][warp_n]     = plo;
            red[row + 8][warp_n] = phi;
        }
    }
    __syncthreads();
    if (tid < 128)
        g_partial[nt][m0 + tid] = red[tid][0] + red[tid][1] + red[tid][2] + red[tid][3];
}

// =====================================================================
// softmax over S per batch
// =====================================================================
__global__ void softmax_kernel(const float* __restrict__ mask,
                               const float* __restrict__ Vb,
                               float* __restrict__ out) {
    const int b   = blockIdx.x;
    const int tid = threadIdx.x;    // 256
    __shared__ float sc[SS];
    __shared__ float red[256];

    const float vb = Vb[0];
    float lmax = -1e38f;
#pragma unroll
    for (int i = 0; i < 8; i++) {
        const int s = tid + i*256;
        float v = g_partial[0][b*SS + s] + g_partial[1][b*SS + s]
                + g_partial[2][b*SS + s] + g_partial[3][b*SS + s] + vb;
        v += (1.0f - mask[b*SS + s]) * -1e30f;
        sc[s] = v;
        lmax = fmaxf(lmax, v);
    }
    red[tid] = lmax;
    __syncthreads();
    for (int st = 128; st > 0; st >>= 1) {
        if (tid < st) red[tid] = fmaxf(red[tid], red[tid + st]);
        __syncthreads();
    }
    const float m = red[0];
    __syncthreads();

    float lsum = 0.f;
#pragma unroll
    for (int i = 0; i < 8; i++) {
        const int s = tid + i*256;
        float e = expf(sc[s] - m);
        sc[s] = e;
        lsum += e;
    }
    red[tid] = lsum;
    __syncthreads();
    for (int st = 128; st > 0; st >>= 1) {
        if (tid < st) red[tid] += red[tid + st];
        __syncthreads();
    }
    const float inv = 1.0f / red[0];
#pragma unroll
    for (int i = 0; i < 8; i++) {
        const int s = tid + i*256;
        out[BB*DD + b*SS + s] = sc[s] * inv;
    }
}

// =====================================================================
// context partials + reduce
// =====================================================================
__global__ void ctx_part_kernel(const float* __restrict__ passage,
                                const float* __restrict__ out_r) {
    const int c = blockIdx.x;
    const int b = blockIdx.y;
    const int d = threadIdx.x;
    __shared__ float w_s[128];
    if (d < 128) w_s[d] = out_r[BB*DD + b*SS + c*128 + d];
    __syncthreads();
    float acc = 0.f;
    const float* p = passage + ((size_t)b*SS + c*128) * DD + d;
#pragma unroll 4
    for (int s = 0; s < 128; s++)
        acc = fmaf(w_s[s], p[(size_t)s * DD], acc);
    g_ctxpart[(b*16 + c)*DD + d] = acc;
}

__global__ void ctx_reduce(float* __restrict__ out) {
    const int b = blockIdx.x;
    const int d = threadIdx.x;
    float s = 0.f;
#pragma unroll
    for (int c = 0; c < 16; c++) s += g_ctxpart[(b*16 + c)*DD + d];
    out[b*DD + d] = s;
}

// =====================================================================
extern "C" void kernel_launch(void* const* d_in, const int* in_sizes, int n_in,
                              void* d_out, int out_size) {
    const float* passage = (const float*)d_in[0];
    const float* hidden  = (const float*)d_in[1];
    const float* mask    = (const float*)d_in[2];
    const float* W1      = (const float*)d_in[3];
    const float* W2      = (const float*)d_in[4];
    const float* Vw      = (const float*)d_in[5];
    const float* Vb      = (const float*)d_in[6];
    float* out = (float*)d_out;

    hproj_kernel<<<BB, DD>>>(hidden, W2);
    w1split<<<UU, DD>>>(W1);
    score_gemm_tc<<<dim3(NTILES, 512), 512>>>(passage, Vw);
    softmax_kernel<<<BB, 256>>>(mask, Vb, out);
    ctx_part_kernel<<<dim3(16, BB), DD>>>(passage, out);
    ctx_reduce<<<BB, DD>>>(out);
}

// round 4
// speedup vs baseline: 3.0315x; 1.6301x over previous
#include <cuda_runtime.h>
#include <cuda_fp16.h>
#include <cstdint>

#define BB 32
#define SS 2048
#define DD 512
#define UU 512
#define ROWS (BB*SS)          // 65536
#define NTILES 4
#define PITCH 144             // smem row pitch bytes for 64 halfs + pad (conflict-free)

// ---------------- scratch (no allocation allowed) ----------------
__device__ float g_hp[BB*UU];                  // h_proj
__device__ float g_partial[NTILES][ROWS];      // per-n-tile partial scores
__device__ float g_ctxpart[BB*16*DD];          // context partials
__device__ __half g_Bh[UU*DD];                 // W1^T fp16  [u][k]

// ---------------- helpers ----------------
__device__ __forceinline__ uint32_t smem_u32(const void* p) {
    uint32_t a;
    asm("{ .reg .u64 t; cvta.to.shared.u64 t, %1; cvt.u32.u64 %0, t; }" : "=r"(a) : "l"(p));
    return a;
}
__device__ __forceinline__ void ldsm_x4(uint32_t addr, uint32_t &r0, uint32_t &r1,
                                        uint32_t &r2, uint32_t &r3) {
    asm volatile("ldmatrix.sync.aligned.m8n8.x4.shared.b16 {%0,%1,%2,%3}, [%4];"
        : "=r"(r0), "=r"(r1), "=r"(r2), "=r"(r3) : "r"(addr));
}
__device__ __forceinline__ void mma_fp16(float* d, const uint32_t* a,
                                         uint32_t b0, uint32_t b1) {
    asm volatile("mma.sync.aligned.m16n8k16.row.col.f32.f16.f16.f32 "
        "{%0,%1,%2,%3}, {%4,%5,%6,%7}, {%8,%9}, {%0,%1,%2,%3};"
        : "+f"(d[0]), "+f"(d[1]), "+f"(d[2]), "+f"(d[3])
        : "r"(a[0]), "r"(a[1]), "r"(a[2]), "r"(a[3]), "r"(b0), "r"(b1));
}
__device__ __forceinline__ uint32_t pack_h2(float x, float y) {
    __half2 h = __float22half2_rn(make_float2(x, y));
    return *(uint32_t*)&h;
}

// =====================================================================
// h_proj: [B,U] = hidden @ W2   (exact fp32)
// =====================================================================
__global__ void hproj_kernel(const float* __restrict__ hidden,
                             const float* __restrict__ W2) {
    __shared__ float h_s[DD];
    const int b = blockIdx.x;
    h_s[threadIdx.x] = hidden[b*DD + threadIdx.x];
    __syncthreads();
    const int u = threadIdx.x;
    float acc = 0.f;
#pragma unroll 8
    for (int d = 0; d < DD; d++)
        acc = fmaf(h_s[d], W2[d*UU + u], acc);
    g_hp[b*UU + u] = acc;
}

// =====================================================================
// W1 transpose + fp16 convert (coalesced tiled transpose)
// =====================================================================
__global__ void w1half(const float* __restrict__ W1) {
    __shared__ float t[32][33];
    const int tx = threadIdx.x, ty = threadIdx.y;
    const int k = blockIdx.y*32 + ty;
    const int n = blockIdx.x*32 + tx;
    t[ty][tx] = W1[k*UU + n];
    __syncthreads();
    g_Bh[(blockIdx.x*32 + ty)*DD + blockIdx.y*32 + tx] = __float2half(t[tx][ty]);
}

// =====================================================================
// Fused fp16 mma.sync score GEMM: CTA tile 128Mx128N, K=512 (8 chunks of 64)
// 512 threads = 16 warps (4M x 4N), warp tile 32x32.
// Epilogue: tanh + Vw partial reduce.
// =====================================================================
__global__ __launch_bounds__(512, 1)
void score_gemm_tc(const float* __restrict__ passage, const float* __restrict__ Vw) {
    __shared__ __align__(16) char sA[128*PITCH];
    __shared__ __align__(16) char sB[128*PITCH];
    __shared__ float hp_s[128];
    __shared__ float vw_s[128];
    __shared__ float red[128][4];

    const int nt = blockIdx.x;       // 0..3
    const int mt = blockIdx.y;       // 0..511
    const int n0 = nt * 128;
    const int m0 = mt * 128;
    const int b  = mt >> 4;
    const int tid = threadIdx.x;
    const int wid = tid >> 5;
    const int lid = tid & 31;
    const int warp_m = wid >> 2;     // 0..3
    const int warp_n = wid & 3;      // 0..3

    if (tid < 128) {
        hp_s[tid] = g_hp[b*UU + n0 + tid];
        vw_s[tid] = Vw[n0 + tid];
    }

    const uint32_t uA = smem_u32(sA), uB = smem_u32(sB);

    // A: 4 threads/row, each 16 consecutive floats
    const int arow = tid >> 2;
    const int akq  = (tid & 3) * 16;
    const float* aptr = passage + (size_t)(m0 + arow) * DD + akq;
    const uint32_t a_sts = (uint32_t)(arow * PITCH + akq * 2);
    // B: 4 threads/row, each 16 consecutive halfs (32B)
    const int brow = tid >> 2;
    const int bkq  = (tid & 3) * 16;
    const __half* bptr = g_Bh + (size_t)(n0 + brow) * DD + bkq;
    const uint32_t b_sts = (uint32_t)(brow * PITCH + bkq * 2);

    // ldmatrix per-thread addresses
    const int lm_row = (lid & 7) + ((lid >> 3) & 1) * 8;
    const int lm_kof = (lid >> 4) * 8;
    const uint32_t a_lm0 = (uint32_t)((warp_m*32 + lm_row) * PITCH + lm_kof * 2);
    const uint32_t a_lm1 = (uint32_t)((warp_m*32 + 16 + lm_row) * PITCH + lm_kof * 2);
    const uint32_t b_lm0 = (uint32_t)((warp_n*32 + lm_row) * PITCH + lm_kof * 2);
    const uint32_t b_lm1 = (uint32_t)((warp_n*32 + 16 + lm_row) * PITCH + lm_kof * 2);

    float acc[2][4][4];
#pragma unroll
    for (int i = 0; i < 2; i++)
#pragma unroll
        for (int j = 0; j < 4; j++)
#pragma unroll
            for (int k = 0; k < 4; k++) acc[i][j][k] = 0.f;

    // prefetch chunk 0
    float4 fa0 = *(const float4*)(aptr);
    float4 fa1 = *(const float4*)(aptr + 4);
    float4 fa2 = *(const float4*)(aptr + 8);
    float4 fa3 = *(const float4*)(aptr + 12);
    uint4  ub0 = *(const uint4*)(bptr);
    uint4  ub1 = *(const uint4*)(bptr + 8);

    for (int c = 0; c < 8; c++) {
        // ---- convert A to fp16, store smem ----
        {
            uint4 h0 = make_uint4(pack_h2(fa0.x, fa0.y), pack_h2(fa0.z, fa0.w),
                                  pack_h2(fa1.x, fa1.y), pack_h2(fa1.z, fa1.w));
            uint4 h1 = make_uint4(pack_h2(fa2.x, fa2.y), pack_h2(fa2.z, fa2.w),
                                  pack_h2(fa3.x, fa3.y), pack_h2(fa3.z, fa3.w));
            *(uint4*)(sA + a_sts)      = h0;
            *(uint4*)(sA + a_sts + 16) = h1;
            *(uint4*)(sB + b_sts)      = ub0;
            *(uint4*)(sB + b_sts + 16) = ub1;
        }
        __syncthreads();

        if (c < 7) {   // prefetch next chunk
            const float* ap = aptr + (c+1)*64;
            fa0 = *(const float4*)(ap);
            fa1 = *(const float4*)(ap + 4);
            fa2 = *(const float4*)(ap + 8);
            fa3 = *(const float4*)(ap + 12);
            ub0 = *(const uint4*)(bptr + (c+1)*64);
            ub1 = *(const uint4*)(bptr + (c+1)*64 + 8);
        }

        // ---- compute: four k16 steps ----
#pragma unroll
        for (int ks = 0; ks < 4; ks++) {
            const uint32_t ko = ks * 32;   // 16 halfs * 2 bytes
            uint32_t ah[2][4];
            ldsm_x4(uA + a_lm0 + ko, ah[0][0], ah[0][1], ah[0][2], ah[0][3]);
            ldsm_x4(uA + a_lm1 + ko, ah[1][0], ah[1][1], ah[1][2], ah[1][3]);

            uint32_t bh[4][2];
            {
                uint32_t r0, r1, r2, r3;
                ldsm_x4(uB + b_lm0 + ko, r0, r1, r2, r3);
                bh[0][0] = r0; bh[0][1] = r2; bh[1][0] = r1; bh[1][1] = r3;
                ldsm_x4(uB + b_lm1 + ko, r0, r1, r2, r3);
                bh[2][0] = r0; bh[2][1] = r2; bh[3][0] = r1; bh[3][1] = r3;
            }

#pragma unroll
            for (int mf = 0; mf < 2; mf++)
#pragma unroll
                for (int nf = 0; nf < 4; nf++)
                    mma_fp16(acc[mf][nf], ah[mf], bh[nf][0], bh[nf][1]);
        }
        __syncthreads();
    }

    // ---- epilogue: tanh + Vw reduce ----
#pragma unroll
    for (int mf = 0; mf < 2; mf++) {
        float plo = 0.f, phi = 0.f;
#pragma unroll
        for (int nf = 0; nf < 4; nf++) {
            const int n = warp_n*32 + nf*8 + (lid & 3)*2;
            const float* cc = acc[mf][nf];
            plo = fmaf(tanhf(cc[0] + hp_s[n]),   vw_s[n],   plo);
            plo = fmaf(tanhf(cc[1] + hp_s[n+1]), vw_s[n+1], plo);
            phi = fmaf(tanhf(cc[2] + hp_s[n]),   vw_s[n],   phi);
            phi = fmaf(tanhf(cc[3] + hp_s[n+1]), vw_s[n+1], phi);
        }
        plo += __shfl_xor_sync(0xffffffff, plo, 1);
        plo += __shfl_xor_sync(0xffffffff, plo, 2);
        phi += __shfl_xor_sync(0xffffffff, phi, 1);
        phi += __shfl_xor_sync(0xffffffff, phi, 2);
        if ((lid & 3) == 0) {
            const int row = warp_m*32 + mf*16 + (lid >> 2);
            red[row][warp_n]     = plo;
            red[row + 8][warp_n] = phi;
        }
    }
    __syncthreads();
    if (tid < 128)
        g_partial[nt][m0 + tid] = red[tid][0] + red[tid][1] + red[tid][2] + red[tid][3];
}

// =====================================================================
// softmax over S per batch
// =====================================================================
__global__ void softmax_kernel(const float* __restrict__ mask,
                               const float* __restrict__ Vb,
                               float* __restrict__ out) {
    const int b   = blockIdx.x;
    const int tid = threadIdx.x;    // 256
    __shared__ float sc[SS];
    __shared__ float red[256];

    const float vb = Vb[0];
    float lmax = -1e38f;
#pragma unroll
    for (int i = 0; i < 8; i++) {
        const int s = tid + i*256;
        float v = g_partial[0][b*SS + s] + g_partial[1][b*SS + s]
                + g_partial[2][b*SS + s] + g_partial[3][b*SS + s] + vb;
        v += (1.0f - mask[b*SS + s]) * -1e30f;
        sc[s] = v;
        lmax = fmaxf(lmax, v);
    }
    red[tid] = lmax;
    __syncthreads();
    for (int st = 128; st > 0; st >>= 1) {
        if (tid < st) red[tid] = fmaxf(red[tid], red[tid + st]);
        __syncthreads();
    }
    const float m = red[0];
    __syncthreads();

    float lsum = 0.f;
#pragma unroll
    for (int i = 0; i < 8; i++) {
        const int s = tid + i*256;
        float e = expf(sc[s] - m);
        sc[s] = e;
        lsum += e;
    }
    red[tid] = lsum;
    __syncthreads();
    for (int st = 128; st > 0; st >>= 1) {
        if (tid < st) red[tid] += red[tid + st];
        __syncthreads();
    }
    const float inv = 1.0f / red[0];
#pragma unroll
    for (int i = 0; i < 8; i++) {
        const int s = tid + i*256;
        out[BB*DD + b*SS + s] = sc[s] * inv;
    }
}

// =====================================================================
// context partials: float4 loads, 4-way row split for MLP
// =====================================================================
__global__ __launch_bounds__(512)
void ctx_part_kernel(const float* __restrict__ passage,
                     const float* __restrict__ out_r) {
    const int c = blockIdx.x;        // 16 s-chunks of 128
    const int b = blockIdx.y;        // 32
    const int tid = threadIdx.x;     // 512
    const int d4  = tid & 127;       // float4 column
    const int grp = tid >> 7;        // 0..3 row group
    __shared__ float w_s[128];
    __shared__ float4 redc[4][128];

    if (tid < 128) w_s[tid] = out_r[BB*DD + b*SS + c*128 + tid];
    __syncthreads();

    float4 acc = make_float4(0.f, 0.f, 0.f, 0.f);
    const float4* p = (const float4*)(passage + ((size_t)b*SS + c*128 + grp*32) * DD) + d4;
#pragma unroll 8
    for (int s = 0; s < 32; s++) {
        float4 v = p[(size_t)s * 128];
        const float w = w_s[grp*32 + s];
        acc.x = fmaf(w, v.x, acc.x);
        acc.y = fmaf(w, v.y, acc.y);
        acc.z = fmaf(w, v.z, acc.z);
        acc.w = fmaf(w, v.w, acc.w);
    }
    redc[grp][d4] = acc;
    __syncthreads();

    if (tid < 128) {
        float4 a0 = redc[0][tid], a1 = redc[1][tid], a2 = redc[2][tid], a3 = redc[3][tid];
        float4 r = make_float4(a0.x+a1.x+a2.x+a3.x, a0.y+a1.y+a2.y+a3.y,
                               a0.z+a1.z+a2.z+a3.z, a0.w+a1.w+a2.w+a3.w);
        *(float4*)(g_ctxpart + (size_t)(b*16 + c)*DD + tid*4) = r;
    }
}

__global__ void ctx_reduce(float* __restrict__ out) {
    const int b = blockIdx.x;
    const int d = threadIdx.x;
    float s = 0.f;
#pragma unroll
    for (int c = 0; c < 16; c++) s += g_ctxpart[(b*16 + c)*DD + d];
    out[b*DD + d] = s;
}

// =====================================================================
extern "C" void kernel_launch(void* const* d_in, const int* in_sizes, int n_in,
                              void* d_out, int out_size) {
    const float* passage = (const float*)d_in[0];
    const float* hidden  = (const float*)d_in[1];
    const float* mask    = (const float*)d_in[2];
    const float* W1      = (const float*)d_in[3];
    const float* W2      = (const float*)d_in[4];
    const float* Vw      = (const float*)d_in[5];
    const float* Vb      = (const float*)d_in[6];
    float* out = (float*)d_out;

    hproj_kernel<<<BB, DD>>>(hidden, W2);
    w1half<<<dim3(16,16), dim3(32,32)>>>(W1);
    score_gemm_tc<<<dim3(NTILES, 512), 512>>>(passage, Vw);
    softmax_kernel<<<BB, 256>>>(mask, Vb, out);
    ctx_part_kernel<<<dim3(16, BB), 512>>>(passage, out);
    ctx_reduce<<<BB, DD>>>(out);
}

// round 5
// speedup vs baseline: 3.1683x; 1.0451x over previous
#include <cuda_runtime.h>
#include <cuda_fp16.h>
#include <cstdint>

#define BB 32
#define SS 2048
#define DD 512
#define UU 512
#define ROWS (BB*SS)          // 65536
#define NTILES 4
#define PITCH 144             // smem row pitch bytes: 64 halfs (128B) + 16B pad

// dynamic smem layout for score kernel
#define SM_A0   0
#define SM_A1   18432
#define SM_B0   36864
#define SM_B1   55296
#define SM_HP   73728
#define SM_VW   74240
#define SM_RED  74752
#define SM_SCORE_BYTES 76800

// ---------------- scratch (no allocation allowed) ----------------
__device__ float g_hp[BB*UU];                  // h_proj
__device__ float g_partial[NTILES][ROWS];      // per-n-tile partial scores
__device__ float g_ctxpart[BB*16*DD];          // context partials
__device__ __half g_Bh[UU*DD];                 // W1^T fp16  [u][k]

// ---------------- helpers ----------------
__device__ __forceinline__ uint32_t smem_u32(const void* p) {
    uint32_t a;
    asm("{ .reg .u64 t; cvta.to.shared.u64 t, %1; cvt.u32.u64 %0, t; }" : "=r"(a) : "l"(p));
    return a;
}
__device__ __forceinline__ void ldsm_x4(uint32_t addr, uint32_t &r0, uint32_t &r1,
                                        uint32_t &r2, uint32_t &r3) {
    asm volatile("ldmatrix.sync.aligned.m8n8.x4.shared.b16 {%0,%1,%2,%3}, [%4];"
        : "=r"(r0), "=r"(r1), "=r"(r2), "=r"(r3) : "r"(addr));
}
__device__ __forceinline__ void mma_fp16(float* d, const uint32_t* a,
                                         uint32_t b0, uint32_t b1) {
    asm volatile("mma.sync.aligned.m16n8k16.row.col.f32.f16.f16.f32 "
        "{%0,%1,%2,%3}, {%4,%5,%6,%7}, {%8,%9}, {%0,%1,%2,%3};"
        : "+f"(d[0]), "+f"(d[1]), "+f"(d[2]), "+f"(d[3])
        : "r"(a[0]), "r"(a[1]), "r"(a[2]), "r"(a[3]), "r"(b0), "r"(b1));
}
__device__ __forceinline__ uint32_t pack_h2(float x, float y) {
    __half2 h = __float22half2_rn(make_float2(x, y));
    return *(uint32_t*)&h;
}

// =====================================================================
// h_proj: [B,U] = hidden @ W2   (exact fp32)
// =====================================================================
__global__ void hproj_kernel(const float* __restrict__ hidden,
                             const float* __restrict__ W2) {
    __shared__ float h_s[DD];
    const int b = blockIdx.x;
    h_s[threadIdx.x] = hidden[b*DD + threadIdx.x];
    __syncthreads();
    const int u = threadIdx.x;
    float acc = 0.f;
#pragma unroll 8
    for (int d = 0; d < DD; d++)
        acc = fmaf(h_s[d], W2[d*UU + u], acc);
    g_hp[b*UU + u] = acc;
}

// =====================================================================
// W1 transpose + fp16 convert
// =====================================================================
__global__ void w1half(const float* __restrict__ W1) {
    __shared__ float t[32][33];
    const int tx = threadIdx.x, ty = threadIdx.y;
    const int k = blockIdx.y*32 + ty;
    const int n = blockIdx.x*32 + tx;
    t[ty][tx] = W1[k*UU + n];
    __syncthreads();
    g_Bh[(blockIdx.x*32 + ty)*DD + blockIdx.y*32 + tx] = __float2half(t[tx][ty]);
}

// =====================================================================
// Fused fp16 mma.sync score GEMM, double-buffered pipeline.
// CTA tile 128Mx128N, K=512 (8 chunks of 64). 16 warps (4Mx4N), warp 32x32.
// =====================================================================
__global__ __launch_bounds__(512, 1)
void score_gemm_tc(const float* __restrict__ passage, const float* __restrict__ Vw) {
    extern __shared__ __align__(16) char dsm[];
    float* hp_s = (float*)(dsm + SM_HP);
    float* vw_s = (float*)(dsm + SM_VW);
    float (*red)[4] = (float(*)[4])(dsm + SM_RED);

    const int nt = blockIdx.x;       // 0..3
    const int mt = blockIdx.y;       // 0..511
    const int n0 = nt * 128;
    const int m0 = mt * 128;
    const int b  = mt >> 4;
    const int tid = threadIdx.x;
    const int wid = tid >> 5;
    const int lid = tid & 31;
    const int warp_m = wid >> 2;
    const int warp_n = wid & 3;

    if (tid < 128) {
        hp_s[tid] = g_hp[b*UU + n0 + tid];
        vw_s[tid] = Vw[n0 + tid];
    }

    const uint32_t uBase = smem_u32(dsm);
    const uint32_t uA[2] = { uBase + SM_A0, uBase + SM_A1 };
    const uint32_t uB[2] = { uBase + SM_B0, uBase + SM_B1 };

    // global load mappings: 4 threads/row, 16 consecutive elements each
    const int grow = tid >> 2;
    const int gkq  = (tid & 3) * 16;
    const float*  aptr = passage + (size_t)(m0 + grow) * DD + gkq;
    const __half* bptr = g_Bh    + (size_t)(n0 + grow) * DD + gkq;
    const uint32_t sts_off = (uint32_t)(grow * PITCH + gkq * 2);

    // ldmatrix per-thread addresses
    const int lm_row = (lid & 7) + ((lid >> 3) & 1) * 8;
    const int lm_kof = (lid >> 4) * 8;
    const uint32_t a_lm0 = (uint32_t)((warp_m*32 + lm_row) * PITCH + lm_kof * 2);
    const uint32_t a_lm1 = (uint32_t)((warp_m*32 + 16 + lm_row) * PITCH + lm_kof * 2);
    const uint32_t b_lm0 = (uint32_t)((warp_n*32 + lm_row) * PITCH + lm_kof * 2);
    const uint32_t b_lm1 = (uint32_t)((warp_n*32 + 16 + lm_row) * PITCH + lm_kof * 2);

    float acc[2][4][4];
#pragma unroll
    for (int i = 0; i < 2; i++)
#pragma unroll
        for (int j = 0; j < 4; j++)
#pragma unroll
            for (int k = 0; k < 4; k++) acc[i][j][k] = 0.f;

    // register prefetch stages: stage s holds chunk with chunk%2==s
    float4 fa[2][4];
    uint4  fb[2][2];
#pragma unroll
    for (int s = 0; s < 2; s++) {
        const float* ap = aptr + s*64;
        fa[s][0] = *(const float4*)(ap);
        fa[s][1] = *(const float4*)(ap + 4);
        fa[s][2] = *(const float4*)(ap + 8);
        fa[s][3] = *(const float4*)(ap + 12);
        fb[s][0] = *(const uint4*)(bptr + s*64);
        fb[s][1] = *(const uint4*)(bptr + s*64 + 8);
    }
    // store chunk 0 -> buffer 0
    {
        uint4 h0 = make_uint4(pack_h2(fa[0][0].x, fa[0][0].y), pack_h2(fa[0][0].z, fa[0][0].w),
                              pack_h2(fa[0][1].x, fa[0][1].y), pack_h2(fa[0][1].z, fa[0][1].w));
        uint4 h1 = make_uint4(pack_h2(fa[0][2].x, fa[0][2].y), pack_h2(fa[0][2].z, fa[0][2].w),
                              pack_h2(fa[0][3].x, fa[0][3].y), pack_h2(fa[0][3].z, fa[0][3].w));
        *(uint4*)(dsm + SM_A0 + sts_off)      = h0;
        *(uint4*)(dsm + SM_A0 + sts_off + 16) = h1;
        *(uint4*)(dsm + SM_B0 + sts_off)      = fb[0][0];
        *(uint4*)(dsm + SM_B0 + sts_off + 16) = fb[0][1];
    }
    __syncthreads();

    for (int c = 0; c < 8; c++) {
        const int cur = c & 1;
        const int nxt = cur ^ 1;

        // 1) issue global loads for chunk c+2 into stage[cur] (chunk c already in smem)
        if (c + 2 < 8) {
            const float* ap = aptr + (c+2)*64;
            fa[cur][0] = *(const float4*)(ap);
            fa[cur][1] = *(const float4*)(ap + 4);
            fa[cur][2] = *(const float4*)(ap + 8);
            fa[cur][3] = *(const float4*)(ap + 12);
            fb[cur][0] = *(const uint4*)(bptr + (c+2)*64);
            fb[cur][1] = *(const uint4*)(bptr + (c+2)*64 + 8);
        }

        // 2) compute chunk c from buf[cur]
#pragma unroll
        for (int ks = 0; ks < 4; ks++) {
            const uint32_t ko = ks * 32;
            uint32_t ah[2][4];
            ldsm_x4(uA[cur] + a_lm0 + ko, ah[0][0], ah[0][1], ah[0][2], ah[0][3]);
            ldsm_x4(uA[cur] + a_lm1 + ko, ah[1][0], ah[1][1], ah[1][2], ah[1][3]);
            uint32_t bh[4][2];
            {
                uint32_t r0, r1, r2, r3;
                ldsm_x4(uB[cur] + b_lm0 + ko, r0, r1, r2, r3);
                bh[0][0] = r0; bh[0][1] = r2; bh[1][0] = r1; bh[1][1] = r3;
                ldsm_x4(uB[cur] + b_lm1 + ko, r0, r1, r2, r3);
                bh[2][0] = r0; bh[2][1] = r2; bh[3][0] = r1; bh[3][1] = r3;
            }
#pragma unroll
            for (int mf = 0; mf < 2; mf++)
#pragma unroll
                for (int nf = 0; nf < 4; nf++)
                    mma_fp16(acc[mf][nf], ah[mf], bh[nf][0], bh[nf][1]);
        }

        // 3) convert + store chunk c+1 (stage[nxt]) into buf[nxt]
        if (c < 7) {
            uint4 h0 = make_uint4(pack_h2(fa[nxt][0].x, fa[nxt][0].y), pack_h2(fa[nxt][0].z, fa[nxt][0].w),
                                  pack_h2(fa[nxt][1].x, fa[nxt][1].y), pack_h2(fa[nxt][1].z, fa[nxt][1].w));
            uint4 h1 = make_uint4(pack_h2(fa[nxt][2].x, fa[nxt][2].y), pack_h2(fa[nxt][2].z, fa[nxt][2].w),
                                  pack_h2(fa[nxt][3].x, fa[nxt][3].y), pack_h2(fa[nxt][3].z, fa[nxt][3].w));
            char* dA = dsm + (nxt ? SM_A1 : SM_A0) + sts_off;
            char* dB = dsm + (nxt ? SM_B1 : SM_B0) + sts_off;
            *(uint4*)(dA)      = h0;
            *(uint4*)(dA + 16) = h1;
            *(uint4*)(dB)      = fb[nxt][0];
            *(uint4*)(dB + 16) = fb[nxt][1];
        }
        __syncthreads();
    }

    // ---- epilogue: tanh + Vw reduce ----
#pragma unroll
    for (int mf = 0; mf < 2; mf++) {
        float plo = 0.f, phi = 0.f;
#pragma unroll
        for (int nf = 0; nf < 4; nf++) {
            const int n = warp_n*32 + nf*8 + (lid & 3)*2;
            const float* cc = acc[mf][nf];
            plo = fmaf(tanhf(cc[0] + hp_s[n]),   vw_s[n],   plo);
            plo = fmaf(tanhf(cc[1] + hp_s[n+1]), vw_s[n+1], plo);
            phi = fmaf(tanhf(cc[2] + hp_s[n]),   vw_s[n],   phi);
            phi = fmaf(tanhf(cc[3] + hp_s[n+1]), vw_s[n+1], phi);
        }
        plo += __shfl_xor_sync(0xffffffff, plo, 1);
        plo += __shfl_xor_sync(0xffffffff, plo, 2);
        phi += __shfl_xor_sync(0xffffffff, phi, 1);
        phi += __shfl_xor_sync(0xffffffff, phi, 2);
        if ((lid & 3) == 0) {
            const int row = warp_m*32 + mf*16 + (lid >> 2);
            red[row][warp_n]     = plo;
            red[row + 8][warp_n] = phi;
        }
    }
    __syncthreads();
    if (tid < 128)
        g_partial[nt][m0 + tid] = red[tid][0] + red[tid][1] + red[tid][2] + red[tid][3];
}

// =====================================================================
// softmax over S per batch
// =====================================================================
__global__ void softmax_kernel(const float* __restrict__ mask,
                               const float* __restrict__ Vb,
                               float* __restrict__ out) {
    const int b   = blockIdx.x;
    const int tid = threadIdx.x;    // 256
    __shared__ float sc[SS];
    __shared__ float red[256];

    const float vb = Vb[0];
    float lmax = -1e38f;
#pragma unroll
    for (int i = 0; i < 8; i++) {
        const int s = tid + i*256;
        float v = g_partial[0][b*SS + s] + g_partial[1][b*SS + s]
                + g_partial[2][b*SS + s] + g_partial[3][b*SS + s] + vb;
        v += (1.0f - mask[b*SS + s]) * -1e30f;
        sc[s] = v;
        lmax = fmaxf(lmax, v);
    }
    red[tid] = lmax;
    __syncthreads();
    for (int st = 128; st > 0; st >>= 1) {
        if (tid < st) red[tid] = fmaxf(red[tid], red[tid + st]);
        __syncthreads();
    }
    const float m = red[0];
    __syncthreads();

    float lsum = 0.f;
#pragma unroll
    for (int i = 0; i < 8; i++) {
        const int s = tid + i*256;
        float e = expf(sc[s] - m);
        sc[s] = e;
        lsum += e;
    }
    red[tid] = lsum;
    __syncthreads();
    for (int st = 128; st > 0; st >>= 1) {
        if (tid < st) red[tid] += red[tid + st];
        __syncthreads();
    }
    const float inv = 1.0f / red[0];
#pragma unroll
    for (int i = 0; i < 8; i++) {
        const int s = tid + i*256;
        out[BB*DD + b*SS + s] = sc[s] * inv;
    }
}

// =====================================================================
// context partials: float4 loads, 4-way row split
// =====================================================================
__global__ __launch_bounds__(512)
void ctx_part_kernel(const float* __restrict__ passage,
                     const float* __restrict__ out_r) {
    const int c = blockIdx.x;
    const int b = blockIdx.y;
    const int tid = threadIdx.x;
    const int d4  = tid & 127;
    const int grp = tid >> 7;
    __shared__ float w_s[128];
    __shared__ float4 redc[4][128];

    if (tid < 128) w_s[tid] = out_r[BB*DD + b*SS + c*128 + tid];
    __syncthreads();

    float4 acc = make_float4(0.f, 0.f, 0.f, 0.f);
    const float4* p = (const float4*)(passage + ((size_t)b*SS + c*128 + grp*32) * DD) + d4;
#pragma unroll 8
    for (int s = 0; s < 32; s++) {
        float4 v = p[(size_t)s * 128];
        const float w = w_s[grp*32 + s];
        acc.x = fmaf(w, v.x, acc.x);
        acc.y = fmaf(w, v.y, acc.y);
        acc.z = fmaf(w, v.z, acc.z);
        acc.w = fmaf(w, v.w, acc.w);
    }
    redc[grp][d4] = acc;
    __syncthreads();

    if (tid < 128) {
        float4 a0 = redc[0][tid], a1 = redc[1][tid], a2 = redc[2][tid], a3 = redc[3][tid];
        float4 r = make_float4(a0.x+a1.x+a2.x+a3.x, a0.y+a1.y+a2.y+a3.y,
                               a0.z+a1.z+a2.z+a3.z, a0.w+a1.w+a2.w+a3.w);
        *(float4*)(g_ctxpart + (size_t)(b*16 + c)*DD + tid*4) = r;
    }
}

__global__ void ctx_reduce(float* __restrict__ out) {
    const int b = blockIdx.x;
    const int d = threadIdx.x;
    float s = 0.f;
#pragma unroll
    for (int c = 0; c < 16; c++) s += g_ctxpart[(b*16 + c)*DD + d];
    out[b*DD + d] = s;
}

// =====================================================================
extern "C" void kernel_launch(void* const* d_in, const int* in_sizes, int n_in,
                              void* d_out, int out_size) {
    const float* passage = (const float*)d_in[0];
    const float* hidden  = (const float*)d_in[1];
    const float* mask    = (const float*)d_in[2];
    const float* W1      = (const float*)d_in[3];
    const float* W2      = (const float*)d_in[4];
    const float* Vw      = (const float*)d_in[5];
    const float* Vb      = (const float*)d_in[6];
    float* out = (float*)d_out;

    cudaFuncSetAttribute(score_gemm_tc, cudaFuncAttributeMaxDynamicSharedMemorySize, SM_SCORE_BYTES);

    hproj_kernel<<<BB, DD>>>(hidden, W2);
    w1half<<<dim3(16,16), dim3(32,32)>>>(W1);
    score_gemm_tc<<<dim3(NTILES, 512), 512, SM_SCORE_BYTES>>>(passage, Vw);
    softmax_kernel<<<BB, 256>>>(mask, Vb, out);
    ctx_part_kernel<<<dim3(16, BB), 512>>>(passage, out);
    ctx_reduce<<<BB, DD>>>(out);
}

// round 6
// speedup vs baseline: 3.2857x; 1.0371x over previous
#include <cuda_runtime.h>
#include <cuda_fp16.h>
#include <cstdint>

#define BB 32
#define SS 2048
#define DD 512
#define UU 512
#define ROWS (BB*SS)          // 65536
#define NTILES 4
#define PITCH 144             // 64 halfs (128B) + 16B pad; PITCH/16 odd => ldsm conflict-free

// dynamic smem layout: 3 stages of (A 256x144 | B 128x144)
#define STG_BYTES 55296
#define SM_HP  165888
#define SM_VW  166400
#define SM_RED 166912
#define SM_SCORE_BYTES 171008

// ---------------- scratch (no allocation allowed) ----------------
__device__ float g_hp[BB*UU];
__device__ float g_partial[NTILES][ROWS];
__device__ float g_ctxpart[BB*16*DD];
__device__ __half g_Bh[UU*DD];        // W1^T fp16 [u][k]
__device__ __half g_Ah[(size_t)ROWS*DD];  // passage fp16 (64MB)

// ---------------- helpers ----------------
__device__ __forceinline__ uint32_t smem_u32(const void* p) {
    uint32_t a;
    asm("{ .reg .u64 t; cvta.to.shared.u64 t, %1; cvt.u32.u64 %0, t; }" : "=r"(a) : "l"(p));
    return a;
}
__device__ __forceinline__ void ldsm_x4(uint32_t addr, uint32_t &r0, uint32_t &r1,
                                        uint32_t &r2, uint32_t &r3) {
    asm volatile("ldmatrix.sync.aligned.m8n8.x4.shared.b16 {%0,%1,%2,%3}, [%4];"
        : "=r"(r0), "=r"(r1), "=r"(r2), "=r"(r3) : "r"(addr));
}
__device__ __forceinline__ void mma_fp16(float* d, const uint32_t* a,
                                         uint32_t b0, uint32_t b1) {
    asm volatile("mma.sync.aligned.m16n8k16.row.col.f32.f16.f16.f32 "
        "{%0,%1,%2,%3}, {%4,%5,%6,%7}, {%8,%9}, {%0,%1,%2,%3};"
        : "+f"(d[0]), "+f"(d[1]), "+f"(d[2]), "+f"(d[3])
        : "r"(a[0]), "r"(a[1]), "r"(a[2]), "r"(a[3]), "r"(b0), "r"(b1));
}
__device__ __forceinline__ uint32_t pack_h2(float x, float y) {
    __half2 h = __float22half2_rn(make_float2(x, y));
    return *(uint32_t*)&h;
}
__device__ __forceinline__ void cp16(uint32_t d, const void* s) {
    asm volatile("cp.async.cg.shared.global [%0], [%1], 16;" :: "r"(d), "l"(s));
}
__device__ __forceinline__ void cp_commit() { asm volatile("cp.async.commit_group;" ::: "memory"); }
__device__ __forceinline__ void cp_wait1()  { asm volatile("cp.async.wait_group 1;" ::: "memory"); }
__device__ __forceinline__ void cp_wait0()  { asm volatile("cp.async.wait_group 0;" ::: "memory"); }
__device__ __forceinline__ float fast_tanh(float x) {
    float e = __expf(2.0f * x);
    return 1.0f - __fdividef(2.0f, e + 1.0f);
}

// =====================================================================
// passage fp32 -> fp16 (one pass)
// =====================================================================
__global__ __launch_bounds__(512)
void a2h_kernel(const float* __restrict__ p) {
    const size_t i = ((size_t)blockIdx.x * 512 + threadIdx.x) * 8;
    float4 f0 = *(const float4*)(p + i);
    float4 f1 = *(const float4*)(p + i + 4);
    uint4 h = make_uint4(pack_h2(f0.x, f0.y), pack_h2(f0.z, f0.w),
                         pack_h2(f1.x, f1.y), pack_h2(f1.z, f1.w));
    *(uint4*)(g_Ah + i) = h;
}

// =====================================================================
// h_proj: exact fp32
// =====================================================================
__global__ void hproj_kernel(const float* __restrict__ hidden,
                             const float* __restrict__ W2) {
    __shared__ float h_s[DD];
    const int b = blockIdx.x;
    h_s[threadIdx.x] = hidden[b*DD + threadIdx.x];
    __syncthreads();
    const int u = threadIdx.x;
    float acc = 0.f;
#pragma unroll 8
    for (int d = 0; d < DD; d++)
        acc = fmaf(h_s[d], W2[d*UU + u], acc);
    g_hp[b*UU + u] = acc;
}

// =====================================================================
// W1 transpose + fp16
// =====================================================================
__global__ void w1half(const float* __restrict__ W1) {
    __shared__ float t[32][33];
    const int tx = threadIdx.x, ty = threadIdx.y;
    t[ty][tx] = W1[(blockIdx.y*32 + ty)*UU + blockIdx.x*32 + tx];
    __syncthreads();
    g_Bh[(blockIdx.x*32 + ty)*DD + blockIdx.y*32 + tx] = __float2half(t[tx][ty]);
}

// =====================================================================
// Score GEMM: CTA 256Mx128N, K=512 in 8 chunks of 64.
// 16 warps (4Mx4N), warp tile 64x32. cp.async 3-stage, 1 sync/chunk.
// =====================================================================
__global__ __launch_bounds__(512, 1)
void score_gemm_tc(const float* __restrict__ Vw) {
    extern __shared__ __align__(16) char dsm[];
    float* hp_s = (float*)(dsm + SM_HP);
    float* vw_s = (float*)(dsm + SM_VW);
    float (*red)[4] = (float(*)[4])(dsm + SM_RED);

    const int nt = blockIdx.x;       // 0..3
    const int mt = blockIdx.y;       // 0..255
    const int n0 = nt * 128;
    const int m0 = mt * 256;
    const int b  = mt >> 3;          // 2048/256 = 8 mtiles per batch
    const int tid = threadIdx.x;
    const int wid = tid >> 5;
    const int lid = tid & 31;
    const int warp_m = wid >> 2;     // 0..3 (64 rows each)
    const int warp_n = wid & 3;      // 0..3 (32 cols each)

    if (tid < 128) {
        hp_s[tid] = g_hp[b*UU + n0 + tid];
        vw_s[tid] = Vw[n0 + tid];
    }

    const uint32_t uBase = smem_u32(dsm);

    // cp.async mappings
    // A: 2048 chunks of 16B per stage; thread t: row=t>>1, 4x16B at (t&1)*64
    const int arow = tid >> 1;
    const int ahalf = (tid & 1);
    const __half* asrc = g_Ah + (size_t)(m0 + arow) * DD + ahalf * 32;
    const uint32_t adst = (uint32_t)(arow * PITCH + ahalf * 64);
    // B: 1024 chunks; thread t: row=t>>2, 2x16B at (t&3)*32
    const int brow = tid >> 2;
    const int bq   = tid & 3;
    const __half* bsrc = g_Bh + (size_t)(n0 + brow) * DD + bq * 16;
    const uint32_t bdst = (uint32_t)(36864 + brow * PITCH + bq * 32);

    // ldsm addresses
    const int lm_row = (lid & 7) + ((lid >> 3) & 1) * 8;
    const int lm_kof = (lid >> 4) * 8;
    uint32_t a_lm[4];
#pragma unroll
    for (int mf = 0; mf < 4; mf++)
        a_lm[mf] = (uint32_t)((warp_m*64 + mf*16 + lm_row) * PITCH + lm_kof * 2);
    const uint32_t b_lm0 = (uint32_t)(36864 + (warp_n*32 + lm_row) * PITCH + lm_kof * 2);
    const uint32_t b_lm1 = (uint32_t)(36864 + (warp_n*32 + 16 + lm_row) * PITCH + lm_kof * 2);

    float acc[4][4][4];
#pragma unroll
    for (int i = 0; i < 4; i++)
#pragma unroll
        for (int j = 0; j < 4; j++)
#pragma unroll
            for (int k = 0; k < 4; k++) acc[i][j][k] = 0.f;

    // prologue: stage chunks 0,1
#pragma unroll
    for (int c = 0; c < 2; c++) {
        const uint32_t sb = uBase + c * STG_BYTES;
#pragma unroll
        for (int j = 0; j < 4; j++)
            cp16(sb + adst + j*16, asrc + c*64 + j*8);
#pragma unroll
        for (int j = 0; j < 2; j++)
            cp16(sb + bdst + j*16, bsrc + c*64 + j*8);
        cp_commit();
    }

    for (int c = 0; c < 8; c++) {
        const int st = c % 3;
        if (c == 7) cp_wait0(); else cp_wait1();
        __syncthreads();

        // issue chunk c+2 into stage (c+2)%3 (its old contents, chunk c-1, are done)
        if (c + 2 < 8) {
            const uint32_t sb = uBase + ((c + 2) % 3) * STG_BYTES;
#pragma unroll
            for (int j = 0; j < 4; j++)
                cp16(sb + adst + j*16, asrc + (c+2)*64 + j*8);
#pragma unroll
            for (int j = 0; j < 2; j++)
                cp16(sb + bdst + j*16, bsrc + (c+2)*64 + j*8);
            cp_commit();
        }

        // compute chunk c
        const uint32_t sbase = uBase + st * STG_BYTES;
#pragma unroll
        for (int ks = 0; ks < 4; ks++) {
            const uint32_t ko = ks * 32;
            uint32_t ah[4][4];
#pragma unroll
            for (int mf = 0; mf < 4; mf++)
                ldsm_x4(sbase + a_lm[mf] + ko, ah[mf][0], ah[mf][1], ah[mf][2], ah[mf][3]);
            uint32_t bh[4][2];
            {
                uint32_t r0, r1, r2, r3;
                ldsm_x4(sbase + b_lm0 + ko, r0, r1, r2, r3);
                bh[0][0] = r0; bh[0][1] = r2; bh[1][0] = r1; bh[1][1] = r3;
                ldsm_x4(sbase + b_lm1 + ko, r0, r1, r2, r3);
                bh[2][0] = r0; bh[2][1] = r2; bh[3][0] = r1; bh[3][1] = r3;
            }
#pragma unroll
            for (int mf = 0; mf < 4; mf++)
#pragma unroll
                for (int nf = 0; nf < 4; nf++)
                    mma_fp16(acc[mf][nf], ah[mf], bh[nf][0], bh[nf][1]);
        }
    }
    __syncthreads();

    // ---- epilogue: tanh + Vw reduce ----
#pragma unroll
    for (int mf = 0; mf < 4; mf++) {
        float plo = 0.f, phi = 0.f;
#pragma unroll
        for (int nf = 0; nf < 4; nf++) {
            const int n = warp_n*32 + nf*8 + (lid & 3)*2;
            const float* cc = acc[mf][nf];
            plo = fmaf(fast_tanh(cc[0] + hp_s[n]),   vw_s[n],   plo);
            plo = fmaf(fast_tanh(cc[1] + hp_s[n+1]), vw_s[n+1], plo);
            phi = fmaf(fast_tanh(cc[2] + hp_s[n]),   vw_s[n],   phi);
            phi = fmaf(fast_tanh(cc[3] + hp_s[n+1]), vw_s[n+1], phi);
        }
        plo += __shfl_xor_sync(0xffffffff, plo, 1);
        plo += __shfl_xor_sync(0xffffffff, plo, 2);
        phi += __shfl_xor_sync(0xffffffff, phi, 1);
        phi += __shfl_xor_sync(0xffffffff, phi, 2);
        if ((lid & 3) == 0) {
            const int row = warp_m*64 + mf*16 + (lid >> 2);
            red[row][warp_n]     = plo;
            red[row + 8][warp_n] = phi;
        }
    }
    __syncthreads();
    if (tid < 256)
        g_partial[nt][m0 + tid] = red[tid][0] + red[tid][1] + red[tid][2] + red[tid][3];
}

// =====================================================================
// softmax over S per batch
// =====================================================================
__global__ void softmax_kernel(const float* __restrict__ mask,
                               const float* __restrict__ Vb,
                               float* __restrict__ out) {
    const int b   = blockIdx.x;
    const int tid = threadIdx.x;    // 256
    __shared__ float sc[SS];
    __shared__ float red[256];

    const float vb = Vb[0];
    float lmax = -1e38f;
#pragma unroll
    for (int i = 0; i < 8; i++) {
        const int s = tid + i*256;
        float v = g_partial[0][b*SS + s] + g_partial[1][b*SS + s]
                + g_partial[2][b*SS + s] + g_partial[3][b*SS + s] + vb;
        v += (1.0f - mask[b*SS + s]) * -1e30f;
        sc[s] = v;
        lmax = fmaxf(lmax, v);
    }
    red[tid] = lmax;
    __syncthreads();
    for (int st = 128; st > 0; st >>= 1) {
        if (tid < st) red[tid] = fmaxf(red[tid], red[tid + st]);
        __syncthreads();
    }
    const float m = red[0];
    __syncthreads();

    float lsum = 0.f;
#pragma unroll
    for (int i = 0; i < 8; i++) {
        const int s = tid + i*256;
        float e = expf(sc[s] - m);
        sc[s] = e;
        lsum += e;
    }
    red[tid] = lsum;
    __syncthreads();
    for (int st = 128; st > 0; st >>= 1) {
        if (tid < st) red[tid] += red[tid + st];
        __syncthreads();
    }
    const float inv = 1.0f / red[0];
#pragma unroll
    for (int i = 0; i < 8; i++) {
        const int s = tid + i*256;
        out[BB*DD + b*SS + s] = sc[s] * inv;
    }
}

// =====================================================================
// context partials + reduce (fp32 passage)
// =====================================================================
__global__ __launch_bounds__(512)
void ctx_part_kernel(const float* __restrict__ passage,
                     const float* __restrict__ out_r) {
    const int c = blockIdx.x;
    const int b = blockIdx.y;
    const int tid = threadIdx.x;
    const int d4  = tid & 127;
    const int grp = tid >> 7;
    __shared__ float w_s[128];
    __shared__ float4 redc[4][128];

    if (tid < 128) w_s[tid] = out_r[BB*DD + b*SS + c*128 + tid];
    __syncthreads();

    float4 acc = make_float4(0.f, 0.f, 0.f, 0.f);
    const float4* p = (const float4*)(passage + ((size_t)b*SS + c*128 + grp*32) * DD) + d4;
#pragma unroll 8
    for (int s = 0; s < 32; s++) {
        float4 v = p[(size_t)s * 128];
        const float w = w_s[grp*32 + s];
        acc.x = fmaf(w, v.x, acc.x);
        acc.y = fmaf(w, v.y, acc.y);
        acc.z = fmaf(w, v.z, acc.z);
        acc.w = fmaf(w, v.w, acc.w);
    }
    redc[grp][d4] = acc;
    __syncthreads();

    if (tid < 128) {
        float4 a0 = redc[0][tid], a1 = redc[1][tid], a2 = redc[2][tid], a3 = redc[3][tid];
        float4 r = make_float4(a0.x+a1.x+a2.x+a3.x, a0.y+a1.y+a2.y+a3.y,
                               a0.z+a1.z+a2.z+a3.z, a0.w+a1.w+a2.w+a3.w);
        *(float4*)(g_ctxpart + (size_t)(b*16 + c)*DD + tid*4) = r;
    }
}

__global__ void ctx_reduce(float* __restrict__ out) {
    const int b = blockIdx.x;
    const int d = threadIdx.x;
    float s = 0.f;
#pragma unroll
    for (int c = 0; c < 16; c++) s += g_ctxpart[(b*16 + c)*DD + d];
    out[b*DD + d] = s;
}

// =====================================================================
extern "C" void kernel_launch(void* const* d_in, const int* in_sizes, int n_in,
                              void* d_out, int out_size) {
    const float* passage = (const float*)d_in[0];
    const float* hidden  = (const float*)d_in[1];
    const float* mask    = (const float*)d_in[2];
    const float* W1      = (const float*)d_in[3];
    const float* W2      = (const float*)d_in[4];
    const float* Vw      = (const float*)d_in[5];
    const float* Vb      = (const float*)d_in[6];
    float* out = (float*)d_out;

    cudaFuncSetAttribute(score_gemm_tc, cudaFuncAttributeMaxDynamicSharedMemorySize, SM_SCORE_BYTES);

    a2h_kernel<<<8192, 512>>>(passage);
    hproj_kernel<<<BB, DD>>>(hidden, W2);
    w1half<<<dim3(16,16), dim3(32,32)>>>(W1);
    score_gemm_tc<<<dim3(NTILES, 256), 512, SM_SCORE_BYTES>>>(Vw);
    softmax_kernel<<<BB, 256>>>(mask, Vb, out);
    ctx_part_kernel<<<dim3(16, BB), 512>>>(passage, out);
    ctx_reduce<<<BB, DD>>>(out);
}